// round 8
// baseline (speedup 1.0000x reference)
#include <cuda_runtime.h>
#include <cstdint>

#define BB 8
#define NN 256
#define HH 128
#define EPSF 1e-20f

#define GRIDSZ 1024
#define TPB    256

// Scratch (allocation-free rule: __device__ globals)
__device__ float g_Ux[BB * NN * HH];
__device__ float g_Vx[BB * NN * HH];
__device__ unsigned int g_bar;   // monotonic across graph replays

__device__ __forceinline__ float dot4(float4 a, float4 b, float c) {
    return fmaf(a.x, b.x, fmaf(a.y, b.y, fmaf(a.z, b.z, fmaf(a.w, b.w, c))));
}

// ---------------------------------------------------------------------------
// FUSED: linear + grid barrier + R6-proven edge loop, one launch.
// R7 lesson: fusion kills the ~15us two-kernel gap (total==kernel time).
// R6 lesson: register loop at 7 blocks/SM (regs<=36) = best edge (54us).
// grid 1024 @ 7/SM -> capacity 1036 >= 1024 -> all resident, barrier safe,
// single wave.
//
// Phase 1: blocks 0..255 compute linear, 8 rows each; thread t: o=t&127,
//          sel=t>>7 (U or V). Blocks 256+ skip to barrier.
// Phase 2: 8 warps = 2 tiles x 4 j-quarters; lane = float4 h-slice;
//          __ldcs streams eg (read-once), Vx via L2/L1.
// ---------------------------------------------------------------------------
__global__ __launch_bounds__(TPB, 7) void fused_kernel(
    const float* __restrict__ x, const float* __restrict__ eg,
    const float* __restrict__ mask,
    const float* __restrict__ Uw, const float* __restrict__ Ub,
    const float* __restrict__ Vw, const float* __restrict__ Vb,
    float* __restrict__ out)
{
    __shared__ __align__(16) float4 smem_pool[256 + 32];  // xs (phase1) / msk (phase2 head)
    __shared__ float4 sh0[8][32];
    __shared__ float4 sh1[8][32];

    const int t = threadIdx.x;

    // ---------------- Phase 1: linear (blocks 0..255 only) ----------------
    if (blockIdx.x < 256) {
        float4* xs = smem_pool;                     // 8 rows x 32 float4 = 4KB
        const int r0 = blockIdx.x * 8;
        xs[t] = reinterpret_cast<const float4*>(x)[(size_t)r0 * 32 + t];
        __syncthreads();

        const int o = t & 127, sel = t >> 7;
        const float4* W4 = reinterpret_cast<const float4*>(sel ? Vw : Uw) + (size_t)o * 32;
        const float bias = sel ? Vb[o] : Ub[o];
        float* dst = sel ? g_Vx : g_Ux;

        float acc[8];
#pragma unroll
        for (int r = 0; r < 8; r++) acc[r] = 0.f;

#pragma unroll 4
        for (int k = 0; k < 32; k++) {
            const float4 wv = W4[k];
#pragma unroll
            for (int r = 0; r < 8; r++)
                acc[r] = dot4(xs[r * 32 + k], wv, acc[r]);
        }
#pragma unroll
        for (int r = 0; r < 8; r++) {
            const int row = r0 + r;
            dst[(size_t)row * HH + o] = mask[row] * (acc[r] + bias);
        }
    }

    // ---------------- Grid-wide barrier (monotonic, replay-safe) ----------
    __threadfence();
    __syncthreads();
    if (t == 0) {
        const unsigned int ticket = atomicAdd(&g_bar, 1u);
        const unsigned int target = ticket - (ticket % GRIDSZ) + GRIDSZ;
        for (;;) {
            unsigned int cur;
            asm volatile("ld.acquire.gpu.global.u32 %0, [%1];" : "=r"(cur) : "l"(&g_bar));
            if ((int)(cur - target) >= 0) break;
            __nanosleep(64);
        }
    }
    __syncthreads();

    // ---------------- Phase 2: edge (R6 loop, verbatim layout) ------------
    const int lane = t & 31;
    const int w    = t >> 5;            // 0..7
    const int tw   = w >> 2;            // tile in block: 0..1
    const int q    = w & 3;             // j-quarter: 0..3
    const int bi   = blockIdx.x * 2 + tw;
    const int b    = bi >> 8;           // same b for both tiles (2 | 256)

    float* msk = reinterpret_cast<float*>(smem_pool);   // NN floats = 1KB
    msk[t] = mask[b * NN + t];
    __syncthreads();

    const float4* egp = reinterpret_cast<const float4*>(eg)
                        + (size_t)(bi * NN + q * 64) * (HH / 4) + lane;
    const float4* vxp = reinterpret_cast<const float4*>(g_Vx)
                        + (size_t)(b * NN + q * 64) * (HH / 4) + lane;
    const float* mp = &msk[q * 64];

    float4 s0 = make_float4(0.f, 0.f, 0.f, 0.f);
    float4 s1 = make_float4(0.f, 0.f, 0.f, 0.f);

#pragma unroll 4
    for (int jj = 0; jj < 64; jj++) {
        float4 e = __ldcs(egp); egp += HH / 4;
        const float4 v = *vxp;  vxp += HH / 4;
        const float mj = mp[jj];
        e.x *= mj; e.y *= mj; e.z *= mj; e.w *= mj;
        s0.x += e.x; s0.y += e.y; s0.z += e.z; s0.w += e.w;
        s1.x = fmaf(e.x, v.x, s1.x);
        s1.y = fmaf(e.y, v.y, s1.y);
        s1.z = fmaf(e.z, v.z, s1.z);
        s1.w = fmaf(e.w, v.w, s1.w);
    }

    sh0[w][lane] = s0;
    sh1[w][lane] = s1;
    __syncthreads();

    if (t < 64) {
        const int tile = t >> 5;        // 0..1
        const int l    = t & 31;
        const int base = tile * 4;
        float4 a0 = sh0[base][l];
        float4 a1 = sh1[base][l];
#pragma unroll
        for (int k = 1; k < 4; k++) {
            const float4 b0 = sh0[base + k][l];
            const float4 b1 = sh1[base + k][l];
            a0.x += b0.x; a0.y += b0.y; a0.z += b0.z; a0.w += b0.w;
            a1.x += b1.x; a1.y += b1.y; a1.z += b1.z; a1.w += b1.w;
        }
        const int bi2 = blockIdx.x * 2 + tile;
        const float mi = msk[bi2 & 255];
        const float4 ux = reinterpret_cast<const float4*>(g_Ux)[(size_t)bi2 * 32 + l];
        float4 o;
        o.x = ux.x + (mi * a1.x) / (EPSF + mi * a0.x);
        o.y = ux.y + (mi * a1.y) / (EPSF + mi * a0.y);
        o.z = ux.z + (mi * a1.z) / (EPSF + mi * a0.z);
        o.w = ux.w + (mi * a1.w) / (EPSF + mi * a0.w);
        reinterpret_cast<float4*>(out)[(size_t)bi2 * 32 + l] = o;
    }
}

extern "C" void kernel_launch(void* const* d_in, const int* in_sizes, int n_in,
                              void* d_out, int out_size)
{
    const float* x   = (const float*)d_in[0];
    const float* eg  = (const float*)d_in[1];
    const float* msk = (const float*)d_in[2];
    const float* Uw  = (const float*)d_in[3];
    const float* Ub  = (const float*)d_in[4];
    const float* Vw  = (const float*)d_in[5];
    const float* Vb  = (const float*)d_in[6];
    float* out = (float*)d_out;

    fused_kernel<<<GRIDSZ, TPB>>>(x, eg, msk, Uw, Ub, Vw, Vb, out);
}